// round 9
// baseline (speedup 1.0000x reference)
#include <cuda_runtime.h>

// Single-pass deterministic reduction, "last block finishes".
// R9 shape: deeper per-thread MLP (12x LDG.128 = 96B/thread/iter),
// ~4 CTAs/SM, GRID = 152*4 = 608 = one exact wave. Fewer CTAs contending
// for the L1tex queue, more outstanding lines per warp.

#define GRID  608           // 152 SMs * 4 resident CTAs @ ~60 regs
#define BLOCK 256

__device__ float          g_partials[GRID];
__device__ unsigned int   g_ticket = 0;

__global__ void __launch_bounds__(BLOCK)
dist_mean_kernel(const char* __restrict__ pbase, const char* __restrict__ tbase,
                 int niters,             // max grid-stride iterations
                 int nbytes,             // total bytes per input
                 double inv_count,
                 float* __restrict__ out)
{
    // Each thread owns 96 bytes (8 triplets = 6 float4) per iteration.
    const int tid0   = (blockIdx.x * BLOCK + threadIdx.x) * 96;
    const int sbytes = GRID * BLOCK * 96;

    const char* pp = pbase + tid0;
    const char* tt = tbase + tid0;
    int off = tid0;

    float acc = 0.0f;
    for (int i = 0; i < niters; i++) {
        if (off + 96 <= nbytes) {
            // front-batched: 12 independent LDG.E.128
            float4 p0 = __ldcs((const float4*)(pp +  0));
            float4 p1 = __ldcs((const float4*)(pp + 16));
            float4 p2 = __ldcs((const float4*)(pp + 32));
            float4 p3 = __ldcs((const float4*)(pp + 48));
            float4 p4 = __ldcs((const float4*)(pp + 64));
            float4 p5 = __ldcs((const float4*)(pp + 80));
            float4 t0 = __ldcs((const float4*)(tt +  0));
            float4 t1 = __ldcs((const float4*)(tt + 16));
            float4 t2 = __ldcs((const float4*)(tt + 32));
            float4 t3 = __ldcs((const float4*)(tt + 48));
            float4 t4 = __ldcs((const float4*)(tt + 64));
            float4 t5 = __ldcs((const float4*)(tt + 80));

            float a, b, c;
            a = p0.x - t0.x; b = p0.y - t0.y; c = p0.z - t0.z;
            acc += sqrtf(fmaf(a, a, fmaf(b, b, c * c)));
            a = p0.w - t0.w; b = p1.x - t1.x; c = p1.y - t1.y;
            acc += sqrtf(fmaf(a, a, fmaf(b, b, c * c)));
            a = p1.z - t1.z; b = p1.w - t1.w; c = p2.x - t2.x;
            acc += sqrtf(fmaf(a, a, fmaf(b, b, c * c)));
            a = p2.y - t2.y; b = p2.z - t2.z; c = p2.w - t2.w;
            acc += sqrtf(fmaf(a, a, fmaf(b, b, c * c)));
            a = p3.x - t3.x; b = p3.y - t3.y; c = p3.z - t3.z;
            acc += sqrtf(fmaf(a, a, fmaf(b, b, c * c)));
            a = p3.w - t3.w; b = p4.x - t4.x; c = p4.y - t4.y;
            acc += sqrtf(fmaf(a, a, fmaf(b, b, c * c)));
            a = p4.z - t4.z; b = p4.w - t4.w; c = p5.x - t5.x;
            acc += sqrtf(fmaf(a, a, fmaf(b, b, c * c)));
            a = p5.y - t5.y; b = p5.z - t5.z; c = p5.w - t5.w;
            acc += sqrtf(fmaf(a, a, fmaf(b, b, c * c)));
        } else if (off < nbytes) {
            // tail: first 48B half only (nbytes is a multiple of 48)
            float4 p0 = __ldcs((const float4*)(pp +  0));
            float4 p1 = __ldcs((const float4*)(pp + 16));
            float4 p2 = __ldcs((const float4*)(pp + 32));
            float4 t0 = __ldcs((const float4*)(tt +  0));
            float4 t1 = __ldcs((const float4*)(tt + 16));
            float4 t2 = __ldcs((const float4*)(tt + 32));
            float a, b, c;
            a = p0.x - t0.x; b = p0.y - t0.y; c = p0.z - t0.z;
            acc += sqrtf(fmaf(a, a, fmaf(b, b, c * c)));
            a = p0.w - t0.w; b = p1.x - t1.x; c = p1.y - t1.y;
            acc += sqrtf(fmaf(a, a, fmaf(b, b, c * c)));
            a = p1.z - t1.z; b = p1.w - t1.w; c = p2.x - t2.x;
            acc += sqrtf(fmaf(a, a, fmaf(b, b, c * c)));
            a = p2.y - t2.y; b = p2.z - t2.z; c = p2.w - t2.w;
            acc += sqrtf(fmaf(a, a, fmaf(b, b, c * c)));
        }
        pp  += sbytes;
        tt  += sbytes;
        off += sbytes;
    }

    // intra-warp reduce
    #pragma unroll
    for (int o = 16; o > 0; o >>= 1)
        acc += __shfl_down_sync(0xffffffffu, acc, o);

    __shared__ float sm[BLOCK / 32];
    if ((threadIdx.x & 31) == 0) sm[threadIdx.x >> 5] = acc;
    __syncthreads();

    __shared__ bool s_last;
    if (threadIdx.x < 32) {
        float v = (threadIdx.x < BLOCK / 32) ? sm[threadIdx.x] : 0.0f;
        #pragma unroll
        for (int o = 4; o > 0; o >>= 1)
            v += __shfl_down_sync(0xffffffffu, v, o);
        if (threadIdx.x == 0) {
            g_partials[blockIdx.x] = v;
            __threadfence();
            unsigned int tk = atomicInc(&g_ticket, GRID - 1);
            s_last = (tk == GRID - 1);
        }
    }
    __syncthreads();

    if (!s_last) return;

    // ---- last block: deterministic final reduce ----
    double dacc = 0.0;
    #pragma unroll
    for (int i = threadIdx.x; i < GRID; i += BLOCK)
        dacc += (double)g_partials[i];

    #pragma unroll
    for (int o = 16; o > 0; o >>= 1)
        dacc += __shfl_down_sync(0xffffffffu, dacc, o);

    __shared__ double dsm[BLOCK / 32];
    if ((threadIdx.x & 31) == 0) dsm[threadIdx.x >> 5] = dacc;
    __syncthreads();

    if (threadIdx.x == 0) {
        double v = 0.0;
        #pragma unroll
        for (int i = 0; i < BLOCK / 32; i++) v += dsm[i];
        out[0] = (float)(v * inv_count);
    }
}

extern "C" void kernel_launch(void* const* d_in, const int* in_sizes, int n_in,
                              void* d_out, int out_size)
{
    const char* pred = (const char*)d_in[0];
    const char* targ = (const char*)d_in[1];
    float* out = (float*)d_out;

    const int n_elem  = in_sizes[0];               // B * 63 = 66,060,288
    const int nbytes  = n_elem * 4;                // 264,241,152 (multiple of 48)
    const int per_it  = GRID * BLOCK * 96;
    const int niters  = (nbytes + per_it - 1) / per_it;
    const long long n_dists = (long long)n_elem / 3;
    const double inv_cnt = 1.0 / (double)n_dists;

    dist_mean_kernel<<<GRID, BLOCK>>>(pred, targ, niters, nbytes, inv_cnt, out);
}

// round 10
// speedup vs baseline: 1.0980x; 1.0980x over previous
#include <cuda_runtime.h>
#include <cuda_pipeline.h>

// Coalesced streaming via cp.async -> smem, triplet-aligned compute from smem.
// Fixes the 3x L1tex wavefront inflation of the per-thread-contiguous LDG
// layout (each warp LDG.128 now touches 4 lines, not 12).
// 2-stage double buffer, 48KB static smem, 4 CTAs/SM, GRID = 152*4 = one wave.

#define GRID       608
#define BLOCK      256
#define TILE_BYTES 12288            // per array per tile = 3072 floats
#define TILE_F     3072

__device__ float        g_partials[GRID];
__device__ unsigned int g_ticket = 0;

__global__ void __launch_bounds__(BLOCK)
dist_mean_kernel(const char* __restrict__ pbase, const char* __restrict__ tbase,
                 int ntiles, int n_elem, double inv_count,
                 float* __restrict__ out)
{
    __shared__ alignas(16) char sbuf[2][2][TILE_BYTES];   // [stage][arr][bytes] = 48KB
    const int tid = threadIdx.x;
    float acc = 0.0f;

    // ---- remainder triplets (n_elem % 3072), handled by block 0 ----
    {
        const int rem_trip = (n_elem - ntiles * TILE_F) / 3;
        if (blockIdx.x == 0 && rem_trip > 0) {
            const float* pf = (const float*)pbase + ntiles * TILE_F;
            const float* tf = (const float*)tbase + ntiles * TILE_F;
            for (int i = tid; i < rem_trip; i += BLOCK) {
                float a = pf[3*i+0] - tf[3*i+0];
                float b = pf[3*i+1] - tf[3*i+1];
                float c = pf[3*i+2] - tf[3*i+2];
                acc += sqrtf(fmaf(a, a, fmaf(b, b, c * c)));
            }
        }
    }

    // ---- prologue: prefetch first tile into stage 0 ----
    int tile = blockIdx.x;
    if (tile < ntiles) {
        const char* gp = pbase + (size_t)tile * TILE_BYTES + tid * 16;
        const char* gt = tbase + (size_t)tile * TILE_BYTES + tid * 16;
        #pragma unroll
        for (int j = 0; j < 3; j++) {
            __pipeline_memcpy_async(&sbuf[0][0][tid*16 + j*4096], gp + j*4096, 16);
            __pipeline_memcpy_async(&sbuf[0][1][tid*16 + j*4096], gt + j*4096, 16);
        }
    }
    __pipeline_commit();

    // ---- main pipeline ----
    int s = 0;
    for (; tile < ntiles; tile += GRID, s ^= 1) {
        __syncthreads();                       // all reads of stage s^1 finished
        const int nxt = tile + GRID;
        if (nxt < ntiles) {
            const char* gp = pbase + (size_t)nxt * TILE_BYTES + tid * 16;
            const char* gt = tbase + (size_t)nxt * TILE_BYTES + tid * 16;
            #pragma unroll
            for (int j = 0; j < 3; j++) {
                __pipeline_memcpy_async(&sbuf[s^1][0][tid*16 + j*4096], gp + j*4096, 16);
                __pipeline_memcpy_async(&sbuf[s^1][1][tid*16 + j*4096], gt + j*4096, 16);
            }
        }
        __pipeline_commit();                   // exactly one group per iteration
        __pipeline_wait_prior(1);              // stage s landed (this thread's part)
        __syncthreads();                       // everyone's stage-s data visible

        // compute: 12 consecutive floats = 4 triplets per thread (conflict-free LDS)
        const float4* ps = (const float4*)&sbuf[s][0][tid * 48];
        const float4* ts = (const float4*)&sbuf[s][1][tid * 48];
        float4 p0 = ps[0], p1 = ps[1], p2 = ps[2];
        float4 t0 = ts[0], t1 = ts[1], t2 = ts[2];

        float a, b, c;
        a = p0.x - t0.x; b = p0.y - t0.y; c = p0.z - t0.z;
        acc += sqrtf(fmaf(a, a, fmaf(b, b, c * c)));
        a = p0.w - t0.w; b = p1.x - t1.x; c = p1.y - t1.y;
        acc += sqrtf(fmaf(a, a, fmaf(b, b, c * c)));
        a = p1.z - t1.z; b = p1.w - t1.w; c = p2.x - t2.x;
        acc += sqrtf(fmaf(a, a, fmaf(b, b, c * c)));
        a = p2.y - t2.y; b = p2.z - t2.z; c = p2.w - t2.w;
        acc += sqrtf(fmaf(a, a, fmaf(b, b, c * c)));
    }

    // ---- block reduce (scratch aliased into sbuf — pipeline fully drained) ----
    __syncthreads();
    float*  sm_f  = (float*)&sbuf[0][0][0];
    int*    sm_fl = (int*)&sbuf[0][0][64];
    double* sm_d  = (double*)&sbuf[0][0][128];

    #pragma unroll
    for (int o = 16; o > 0; o >>= 1)
        acc += __shfl_down_sync(0xffffffffu, acc, o);
    if ((tid & 31) == 0) sm_f[tid >> 5] = acc;
    __syncthreads();

    if (tid < 32) {
        float v = (tid < BLOCK / 32) ? sm_f[tid] : 0.0f;
        #pragma unroll
        for (int o = 4; o > 0; o >>= 1)
            v += __shfl_down_sync(0xffffffffu, v, o);
        if (tid == 0) {
            g_partials[blockIdx.x] = v;
            __threadfence();
            unsigned int tk = atomicInc(&g_ticket, GRID - 1);
            sm_fl[0] = (tk == GRID - 1) ? 1 : 0;
        }
    }
    __syncthreads();
    if (!sm_fl[0]) return;

    // ---- last block: deterministic final reduce ----
    double dacc = 0.0;
    #pragma unroll
    for (int i = tid; i < GRID; i += BLOCK)
        dacc += (double)g_partials[i];

    #pragma unroll
    for (int o = 16; o > 0; o >>= 1)
        dacc += __shfl_down_sync(0xffffffffu, dacc, o);
    if ((tid & 31) == 0) sm_d[tid >> 5] = dacc;
    __syncthreads();

    if (tid == 0) {
        double v = 0.0;
        #pragma unroll
        for (int i = 0; i < BLOCK / 32; i++) v += sm_d[i];
        out[0] = (float)(v * inv_count);
    }
}

extern "C" void kernel_launch(void* const* d_in, const int* in_sizes, int n_in,
                              void* d_out, int out_size)
{
    const char* pred = (const char*)d_in[0];
    const char* targ = (const char*)d_in[1];
    float* out = (float*)d_out;

    const int n_elem = in_sizes[0];            // B * 63 = 66,060,288 = 3072 * 21504
    const int ntiles = n_elem / TILE_F;
    const long long n_dists = (long long)n_elem / 3;
    const double inv_cnt = 1.0 / (double)n_dists;

    dist_mean_kernel<<<GRID, BLOCK>>>(pred, targ, ntiles, n_elem, inv_cnt, out);
}